// round 2
// baseline (speedup 1.0000x reference)
#include <cuda_runtime.h>

// CVScaledDotProductAttention: complex attention with magnitude min-max norm.
// One-pass reformulation: out = (A - mn*B) / (mx - mn)
//   A = sum_k attn_k * v_k,  B = sum_k (attn_k/|attn_k|) * v_k,
//   mn/mx = row min/max of |attn|.  All accumulable in a single k sweep.

#define TQ 64
#define TK 64
#define Dd 64
#define S_LEN 1024
#define NKT 16
#define NTHREADS 256
#define NHEADS 64

// smem layout (float offsets). Kt region is aliased by P/Im (never live together).
#define KSTR 68                 // stride for d-major Q/K tiles (conflict mitigation)
#define QTR_OFF 0               // 64*68 = 4352
#define QTI_OFF 4352
#define KTR_OFF 8704            // union region start
#define KTI_OFF 13056
#define PR_OFF  8704            // P real   [q][k], stride 64
#define PI_OFF  12800           // P imag
#define IM_OFF  16896           // 1/|s|
#define VR_OFF  20992           // V real [k][d], stride 64
#define VI_OFF  25088
#define RMN_OFF 29184
#define RMX_OFF 29248
#define SMEM_FLOATS 29312       // 117,248 bytes

__global__ void __launch_bounds__(NTHREADS)
cvattn_kernel(const float* __restrict__ qr_g, const float* __restrict__ qi_g,
              const float* __restrict__ kr_g, const float* __restrict__ ki_g,
              const float* __restrict__ vr_g, const float* __restrict__ vi_g,
              float* __restrict__ out)
{
    extern __shared__ float sm[];
    const int tid = threadIdx.x;
    const int tx = tid & 15;          // k / d fragment index (16)
    const int ty = tid >> 4;          // q fragment index (16)
    const int qt = blockIdx.x;        // q tile (16)
    const int head = blockIdx.y;      // 64 heads
    const long hb = (long)head * S_LEN * Dd;

    // ---- load Q tile, transposed to [d][q], scaled by 1/TEMPERATURE ----
#pragma unroll
    for (int it = 0; it < 4; ++it) {
        int i  = tid + it * NTHREADS;       // 0..1023 float4 chunks
        int q  = i >> 4;
        int d4 = (i & 15) << 2;
        long g = hb + (long)(qt * TQ + q) * Dd + d4;
        float4 r4 = *(const float4*)(qr_g + g);
        float4 i4 = *(const float4*)(qi_g + g);
        sm[QTR_OFF + (d4 + 0) * KSTR + q] = r4.x * 0.125f;
        sm[QTR_OFF + (d4 + 1) * KSTR + q] = r4.y * 0.125f;
        sm[QTR_OFF + (d4 + 2) * KSTR + q] = r4.z * 0.125f;
        sm[QTR_OFF + (d4 + 3) * KSTR + q] = r4.w * 0.125f;
        sm[QTI_OFF + (d4 + 0) * KSTR + q] = i4.x * 0.125f;
        sm[QTI_OFF + (d4 + 1) * KSTR + q] = i4.y * 0.125f;
        sm[QTI_OFF + (d4 + 2) * KSTR + q] = i4.z * 0.125f;
        sm[QTI_OFF + (d4 + 3) * KSTR + q] = i4.w * 0.125f;
    }
    if (tid < TQ) { sm[RMN_OFF + tid] = 3.0e38f; sm[RMX_OFF + tid] = -3.0e38f; }

    float Ar[4][4], Ai[4][4], Br[4][4], Bi[4][4];
#pragma unroll
    for (int j = 0; j < 4; ++j)
#pragma unroll
        for (int l = 0; l < 4; ++l) { Ar[j][l] = 0.f; Ai[j][l] = 0.f; Br[j][l] = 0.f; Bi[j][l] = 0.f; }

#pragma unroll 1
    for (int kt = 0; kt < NKT; ++kt) {
        __syncthreads();   // prev phase-2 finished with P/V region (and Q loads on kt=0)

        // ---- load K tile transposed to [d][k], V tile natural [k][d] ----
#pragma unroll
        for (int it = 0; it < 4; ++it) {
            int i  = tid + it * NTHREADS;
            int k  = i >> 4;
            int d4 = (i & 15) << 2;
            long g = hb + (long)(kt * TK + k) * Dd + d4;
            float4 r4 = *(const float4*)(kr_g + g);
            float4 i4 = *(const float4*)(ki_g + g);
            sm[KTR_OFF + (d4 + 0) * KSTR + k] = r4.x;
            sm[KTR_OFF + (d4 + 1) * KSTR + k] = r4.y;
            sm[KTR_OFF + (d4 + 2) * KSTR + k] = r4.z;
            sm[KTR_OFF + (d4 + 3) * KSTR + k] = r4.w;
            sm[KTI_OFF + (d4 + 0) * KSTR + k] = i4.x;
            sm[KTI_OFF + (d4 + 1) * KSTR + k] = i4.y;
            sm[KTI_OFF + (d4 + 2) * KSTR + k] = i4.z;
            sm[KTI_OFF + (d4 + 3) * KSTR + k] = i4.w;
            float4 vr4 = *(const float4*)(vr_g + g);
            float4 vi4 = *(const float4*)(vi_g + g);
            *(float4*)&sm[VR_OFF + k * Dd + d4] = vr4;
            *(float4*)&sm[VI_OFF + k * Dd + d4] = vi4;
        }
        __syncthreads();

        // ---- phase 1: complex scores S[4q][4k] per thread ----
        float sr[4][4], si[4][4];
#pragma unroll
        for (int j = 0; j < 4; ++j)
#pragma unroll
            for (int l = 0; l < 4; ++l) { sr[j][l] = 0.f; si[j][l] = 0.f; }

#pragma unroll 4
        for (int d = 0; d < Dd; ++d) {
            float4 qr4 = *(const float4*)&sm[QTR_OFF + d * KSTR + 4 * ty];
            float4 qi4 = *(const float4*)&sm[QTI_OFF + d * KSTR + 4 * ty];
            float4 kr4 = *(const float4*)&sm[KTR_OFF + d * KSTR + 4 * tx];
            float4 ki4 = *(const float4*)&sm[KTI_OFF + d * KSTR + 4 * tx];
            const float qr[4] = {qr4.x, qr4.y, qr4.z, qr4.w};
            const float qi[4] = {qi4.x, qi4.y, qi4.z, qi4.w};
            const float kr[4] = {kr4.x, kr4.y, kr4.z, kr4.w};
            const float ki[4] = {ki4.x, ki4.y, ki4.z, ki4.w};
#pragma unroll
            for (int j = 0; j < 4; ++j)
#pragma unroll
                for (int l = 0; l < 4; ++l) {
                    sr[j][l] = fmaf(qr[j], kr[l], sr[j][l]);
                    sr[j][l] = fmaf(-qi[j], ki[l], sr[j][l]);
                    si[j][l] = fmaf(qr[j], ki[l], si[j][l]);
                    si[j][l] = fmaf(qi[j], kr[l], si[j][l]);
                }
        }
        __syncthreads();   // Kt reads done; P/Im region may be overwritten

        // ---- phase 1.5: magnitudes, row min/max, publish P and 1/|s| ----
        float lmn[4], lmx[4];
#pragma unroll
        for (int j = 0; j < 4; ++j) {
            float imv[4], magv[4];
#pragma unroll
            for (int l = 0; l < 4; ++l) {
                float a = sr[j][l], b = si[j][l];
                float m2 = fmaf(a, a, b * b);
                m2 = fmaxf(m2, 1e-37f);
                float rinv = rsqrtf(m2);
                imv[l]  = rinv;
                magv[l] = m2 * rinv;
            }
            lmn[j] = fminf(fminf(magv[0], magv[1]), fminf(magv[2], magv[3]));
            lmx[j] = fmaxf(fmaxf(magv[0], magv[1]), fmaxf(magv[2], magv[3]));
            int qq = 4 * ty + j;
            *(float4*)&sm[PR_OFF + qq * TK + 4 * tx] = make_float4(sr[j][0], sr[j][1], sr[j][2], sr[j][3]);
            *(float4*)&sm[PI_OFF + qq * TK + 4 * tx] = make_float4(si[j][0], si[j][1], si[j][2], si[j][3]);
            *(float4*)&sm[IM_OFF + qq * TK + 4 * tx] = make_float4(imv[0], imv[1], imv[2], imv[3]);
        }
        // reduce min/max across the 16 tx lanes (xor stays inside 16-lane group)
#pragma unroll
        for (int off = 1; off < 16; off <<= 1) {
#pragma unroll
            for (int j = 0; j < 4; ++j) {
                lmn[j] = fminf(lmn[j], __shfl_xor_sync(0xffffffffu, lmn[j], off));
                lmx[j] = fmaxf(lmx[j], __shfl_xor_sync(0xffffffffu, lmx[j], off));
            }
        }
        if (tx == 0) {
#pragma unroll
            for (int j = 0; j < 4; ++j) {
                int qq = 4 * ty + j;
                sm[RMN_OFF + qq] = fminf(sm[RMN_OFF + qq], lmn[j]);
                sm[RMX_OFF + qq] = fmaxf(sm[RMX_OFF + qq], lmx[j]);
            }
        }
        __syncthreads();

        // ---- phase 2: A += P*V, B += (P/|P|)*V over this k tile ----
#pragma unroll 2
        for (int k = 0; k < TK; ++k) {
            float pr[4], pi[4], im[4];
#pragma unroll
            for (int j = 0; j < 4; ++j) {
                int qq = 4 * ty + j;                        // broadcast loads
                pr[j] = sm[PR_OFF + qq * TK + k];
                pi[j] = sm[PI_OFF + qq * TK + k];
                im[j] = sm[IM_OFF + qq * TK + k];
            }
            float4 vr4 = *(const float4*)&sm[VR_OFF + k * Dd + 4 * tx];
            float4 vi4 = *(const float4*)&sm[VI_OFF + k * Dd + 4 * tx];
            const float vr[4] = {vr4.x, vr4.y, vr4.z, vr4.w};
            const float vi[4] = {vi4.x, vi4.y, vi4.z, vi4.w};
            float ur[4], ui[4];
#pragma unroll
            for (int j = 0; j < 4; ++j) { ur[j] = pr[j] * im[j]; ui[j] = pi[j] * im[j]; }
#pragma unroll
            for (int j = 0; j < 4; ++j)
#pragma unroll
                for (int l = 0; l < 4; ++l) {
                    Ar[j][l] = fmaf(pr[j], vr[l], Ar[j][l]);
                    Ar[j][l] = fmaf(-pi[j], vi[l], Ar[j][l]);
                    Ai[j][l] = fmaf(pr[j], vi[l], Ai[j][l]);
                    Ai[j][l] = fmaf(pi[j], vr[l], Ai[j][l]);
                    Br[j][l] = fmaf(ur[j], vr[l], Br[j][l]);
                    Br[j][l] = fmaf(-ui[j], vi[l], Br[j][l]);
                    Bi[j][l] = fmaf(ur[j], vi[l], Bi[j][l]);
                    Bi[j][l] = fmaf(ui[j], vr[l], Bi[j][l]);
                }
        }
    }
    __syncthreads();

    // ---- epilogue: out = (A - mn*B) / (mx - mn) ----
    float* out_r = out;
    float* out_i = out + (long)NHEADS * S_LEN * Dd;
#pragma unroll
    for (int j = 0; j < 4; ++j) {
        int qq = 4 * ty + j;
        float mn = sm[RMN_OFF + qq];
        float mx = sm[RMX_OFF + qq];
        float sc = 1.0f / (mx - mn);
        float4 o_r, o_i;
        o_r.x = (Ar[j][0] - mn * Br[j][0]) * sc;
        o_r.y = (Ar[j][1] - mn * Br[j][1]) * sc;
        o_r.z = (Ar[j][2] - mn * Br[j][2]) * sc;
        o_r.w = (Ar[j][3] - mn * Br[j][3]) * sc;
        o_i.x = (Ai[j][0] - mn * Bi[j][0]) * sc;
        o_i.y = (Ai[j][1] - mn * Bi[j][1]) * sc;
        o_i.z = (Ai[j][2] - mn * Bi[j][2]) * sc;
        o_i.w = (Ai[j][3] - mn * Bi[j][3]) * sc;
        long g = hb + (long)(qt * TQ + qq) * Dd + 4 * tx;
        *(float4*)(out_r + g) = o_r;
        *(float4*)(out_i + g) = o_i;
    }
}

extern "C" void kernel_launch(void* const* d_in, const int* in_sizes, int n_in,
                              void* d_out, int out_size)
{
    const float* qr = (const float*)d_in[0];
    const float* qi = (const float*)d_in[1];
    const float* kr = (const float*)d_in[2];
    const float* ki = (const float*)d_in[3];
    const float* vr = (const float*)d_in[4];
    const float* vi = (const float*)d_in[5];
    float* out = (float*)d_out;

    const int smem_bytes = SMEM_FLOATS * (int)sizeof(float);   // 117,248 B
    cudaFuncSetAttribute(cvattn_kernel,
                         cudaFuncAttributeMaxDynamicSharedMemorySize, smem_bytes);

    dim3 grid(S_LEN / TQ, NHEADS);   // (16 q-tiles, 64 heads)
    cvattn_kernel<<<grid, NTHREADS, smem_bytes>>>(qr, qi, kr, ki, vr, vi, out);
}

// round 3
// speedup vs baseline: 1.0372x; 1.0372x over previous
#include <cuda_runtime.h>

// CVScaledDotProductAttention — one-pass: out = (A - mn*B)/(mx - mn)
//   A = sum_k attn*v, B = sum_k (attn/|attn|)*v, mn/mx = row min/max |attn|.
// Round 3: packed fp32 math via PTX fma.rn.f32x2 (FFMA2; 2 FLOP/issue).

#define S_LEN 1024
#define NHEADS 64
#define NTHREADS 256
#define NKT 16

typedef unsigned long long u64;

__device__ __forceinline__ u64 fma2(u64 a, u64 b, u64 c) {
    u64 d; asm("fma.rn.f32x2 %0, %1, %2, %3;" : "=l"(d) : "l"(a), "l"(b), "l"(c)); return d;
}
__device__ __forceinline__ u64 dup2(float x) {
    u64 d; asm("mov.b64 %0, {%1, %1};" : "=l"(d) : "f"(x)); return d;
}
__device__ __forceinline__ float2 unpack2(u64 p) {
    float2 r; asm("mov.b64 {%0, %1}, %2;" : "=f"(r.x), "=f"(r.y) : "l"(p)); return r;
}

// smem layout in floats. Q dup arrays persist; K region aliased by P region.
#define QRD_OFF 0            // (q,q) dup pairs [d][q]: 4096 pairs = 8192 floats
#define QID_OFF 8192
#define KR_OFF  16384        // K [d][k] swizzled, 4096 floats
#define KI_OFF  20480
#define KIN_OFF 24576        // -ki
#define PR_OFF  16384        // P [k][q] swizzled (aliases K region)
#define PI_OFF  20480
#define UR_OFF  24576        // u = p/|p|
#define UI_OFF  28672
#define VR_OFF  32768        // V [k][d] natural
#define VI_OFF  36864
#define VIN_OFF 40960        // -vi
#define RMN_OFF 45056
#define RMX_OFF 45120
#define SMEM_FLOATS 45184    // 180,736 bytes

__global__ void __launch_bounds__(NTHREADS)
cvattn_kernel(const float* __restrict__ qr_g, const float* __restrict__ qi_g,
              const float* __restrict__ kr_g, const float* __restrict__ ki_g,
              const float* __restrict__ vr_g, const float* __restrict__ vi_g,
              float* __restrict__ out)
{
    extern __shared__ float sm[];
    const int tid = threadIdx.x;
    const int tx = tid & 15;          // k / d fragment (16)
    const int ty = tid >> 4;          // q fragment (16)
    const int qt = blockIdx.x;
    const int head = blockIdx.y;
    const long hb = (long)head * S_LEN * 64;

    // ---- load Q tile as (x,x) dup pairs, transposed [d][q], scaled 1/8 ----
#pragma unroll
    for (int it = 0; it < 4; ++it) {
        int i  = tid + it * NTHREADS;
        int q  = i >> 4;
        int d4 = (i & 15) << 2;
        long g = hb + (long)(qt * 64 + q) * 64 + d4;
        float4 r4 = *(const float4*)(qr_g + g);
        float4 i4 = *(const float4*)(qi_g + g);
        float rr[4] = {r4.x, r4.y, r4.z, r4.w};
        float ii[4] = {i4.x, i4.y, i4.z, i4.w};
#pragma unroll
        for (int j = 0; j < 4; ++j) {
            int d = d4 + j;
            int pidx = d * 64 + (q ^ (d & 0x1C));
            float vr_ = rr[j] * 0.125f, vi_ = ii[j] * 0.125f;
            *(float2*)&sm[QRD_OFF + 2 * pidx] = make_float2(vr_, vr_);
            *(float2*)&sm[QID_OFF + 2 * pidx] = make_float2(vi_, vi_);
        }
    }
    if (tid < 64) { sm[RMN_OFF + tid] = 3.0e38f; sm[RMX_OFF + tid] = -3.0e38f; }

    // packed accumulators: (A[2jp], A[2jp+1]) over q, per l (output d)
    u64 ArP[2][4], AiP[2][4], BrP[2][4], BiP[2][4];
#pragma unroll
    for (int jp = 0; jp < 2; ++jp)
#pragma unroll
        for (int l = 0; l < 4; ++l) { ArP[jp][l] = 0ull; AiP[jp][l] = 0ull; BrP[jp][l] = 0ull; BiP[jp][l] = 0ull; }

#pragma unroll 1
    for (int kt = 0; kt < NKT; ++kt) {
        __syncthreads();   // prev phase-2 done with P/V regions

        // ---- load K transposed [d][k] (+ -ki), V natural [k][d] (+ -vi) ----
#pragma unroll
        for (int it = 0; it < 4; ++it) {
            int i  = tid + it * NTHREADS;
            int k  = i >> 4;
            int d4 = (i & 15) << 2;
            long g = hb + (long)(kt * 64 + k) * 64 + d4;
            float4 r4 = *(const float4*)(kr_g + g);
            float4 i4 = *(const float4*)(ki_g + g);
            float rr[4] = {r4.x, r4.y, r4.z, r4.w};
            float ii[4] = {i4.x, i4.y, i4.z, i4.w};
#pragma unroll
            for (int j = 0; j < 4; ++j) {
                int d = d4 + j;
                int idx = d * 64 + (k ^ (d & 0x1C));
                sm[KR_OFF + idx]  = rr[j];
                sm[KI_OFF + idx]  = ii[j];
                sm[KIN_OFF + idx] = -ii[j];
            }
            float4 vr4 = *(const float4*)(vr_g + g);
            float4 vi4 = *(const float4*)(vi_g + g);
            *(float4*)&sm[VR_OFF + k * 64 + d4] = vr4;
            *(float4*)&sm[VI_OFF + k * 64 + d4] = vi4;
            *(float4*)&sm[VIN_OFF + k * 64 + d4] =
                make_float4(-vi4.x, -vi4.y, -vi4.z, -vi4.w);
        }
        __syncthreads();

        // ---- phase 1: scores; acc packed over k: srP[j][lp]=(sr[j][2lp],sr[j][2lp+1]) ----
        u64 srP[4][2], siP[4][2];
#pragma unroll
        for (int j = 0; j < 4; ++j) { srP[j][0] = srP[j][1] = 0ull; siP[j][0] = siP[j][1] = 0ull; }

#pragma unroll 4
        for (int d = 0; d < 64; ++d) {
            int sw = d & 0x1C;
            const float* qp = sm + QRD_OFF + 2 * (d * 64 + ((4 * ty) ^ sw));
            ulonglong2 qra = *(const ulonglong2*)qp;          // dup pairs j=0,1
            ulonglong2 qrb = *(const ulonglong2*)(qp + 4);    // j=2,3
            const float* qip = sm + QID_OFF + 2 * (d * 64 + ((4 * ty) ^ sw));
            ulonglong2 qia = *(const ulonglong2*)qip;
            ulonglong2 qib = *(const ulonglong2*)(qip + 4);
            int kidx = d * 64 + ((4 * tx) ^ sw);
            ulonglong2 krp = *(const ulonglong2*)&sm[KR_OFF + kidx];   // (kr0,kr1),(kr2,kr3)
            ulonglong2 kip = *(const ulonglong2*)&sm[KI_OFF + kidx];
            ulonglong2 knp = *(const ulonglong2*)&sm[KIN_OFF + kidx];
            u64 qd[4]  = {qra.x, qra.y, qrb.x, qrb.y};
            u64 qdi[4] = {qia.x, qia.y, qib.x, qib.y};
            u64 kr_[2] = {krp.x, krp.y};
            u64 ki_[2] = {kip.x, kip.y};
            u64 kn_[2] = {knp.x, knp.y};
#pragma unroll
            for (int j = 0; j < 4; ++j)
#pragma unroll
                for (int lp = 0; lp < 2; ++lp) {
                    srP[j][lp] = fma2(qd[j],  kr_[lp], srP[j][lp]);
                    srP[j][lp] = fma2(qdi[j], kn_[lp], srP[j][lp]);
                    siP[j][lp] = fma2(qd[j],  ki_[lp], siP[j][lp]);
                    siP[j][lp] = fma2(qdi[j], kr_[lp], siP[j][lp]);
                }
        }
        __syncthreads();   // K reads done; P region may be overwritten

        // ---- phase 1.5: mags, row min/max, publish P and U=P/|P| as [k][q] ----
        float sr[4][4], si[4][4], ur[4][4], ui[4][4];
        float lmn[4], lmx[4];
#pragma unroll
        for (int j = 0; j < 4; ++j) {
            float2 a0 = unpack2(srP[j][0]), a1 = unpack2(srP[j][1]);
            float2 b0 = unpack2(siP[j][0]), b1 = unpack2(siP[j][1]);
            sr[j][0] = a0.x; sr[j][1] = a0.y; sr[j][2] = a1.x; sr[j][3] = a1.y;
            si[j][0] = b0.x; si[j][1] = b0.y; si[j][2] = b1.x; si[j][3] = b1.y;
            float magv[4];
#pragma unroll
            for (int l = 0; l < 4; ++l) {
                float a = sr[j][l], b = si[j][l];
                float m2 = fmaf(a, a, b * b);
                m2 = fmaxf(m2, 1e-37f);
                float rinv = rsqrtf(m2);
                ur[j][l] = a * rinv;
                ui[j][l] = b * rinv;
                magv[l]  = m2 * rinv;
            }
            lmn[j] = fminf(fminf(magv[0], magv[1]), fminf(magv[2], magv[3]));
            lmx[j] = fmaxf(fmaxf(magv[0], magv[1]), fmaxf(magv[2], magv[3]));
        }
#pragma unroll
        for (int l = 0; l < 4; ++l) {
            int k = 4 * tx + l;
            int idx = k * 64 + ((4 * ty) ^ (k & 0x1C));
            *(float4*)&sm[PR_OFF + idx] = make_float4(sr[0][l], sr[1][l], sr[2][l], sr[3][l]);
            *(float4*)&sm[PI_OFF + idx] = make_float4(si[0][l], si[1][l], si[2][l], si[3][l]);
            *(float4*)&sm[UR_OFF + idx] = make_float4(ur[0][l], ur[1][l], ur[2][l], ur[3][l]);
            *(float4*)&sm[UI_OFF + idx] = make_float4(ui[0][l], ui[1][l], ui[2][l], ui[3][l]);
        }
#pragma unroll
        for (int off = 1; off < 16; off <<= 1) {
#pragma unroll
            for (int j = 0; j < 4; ++j) {
                lmn[j] = fminf(lmn[j], __shfl_xor_sync(0xffffffffu, lmn[j], off));
                lmx[j] = fmaxf(lmx[j], __shfl_xor_sync(0xffffffffu, lmx[j], off));
            }
        }
        if (tx == 0) {
#pragma unroll
            for (int j = 0; j < 4; ++j) {
                int qq = 4 * ty + j;
                sm[RMN_OFF + qq] = fminf(sm[RMN_OFF + qq], lmn[j]);
                sm[RMX_OFF + qq] = fmaxf(sm[RMX_OFF + qq], lmx[j]);
            }
        }
        __syncthreads();

        // ---- phase 2: A += P*V, B += U*V (packed over q) ----
#pragma unroll 2
        for (int k = 0; k < 64; ++k) {
            int base = k * 64 + ((4 * ty) ^ (k & 0x1C));
            ulonglong2 pp = *(const ulonglong2*)&sm[PR_OFF + base];  // (pr0,pr1),(pr2,pr3)
            ulonglong2 pq = *(const ulonglong2*)&sm[PI_OFF + base];
            ulonglong2 uu = *(const ulonglong2*)&sm[UR_OFF + base];
            ulonglong2 uw = *(const ulonglong2*)&sm[UI_OFF + base];
            float4 vr4 = *(const float4*)&sm[VR_OFF + k * 64 + 4 * tx];
            float4 vi4 = *(const float4*)&sm[VI_OFF + k * 64 + 4 * tx];
            float4 vn4 = *(const float4*)&sm[VIN_OFF + k * 64 + 4 * tx];
            u64 vrd[4] = {dup2(vr4.x), dup2(vr4.y), dup2(vr4.z), dup2(vr4.w)};
            u64 vid[4] = {dup2(vi4.x), dup2(vi4.y), dup2(vi4.z), dup2(vi4.w)};
            u64 vnd[4] = {dup2(vn4.x), dup2(vn4.y), dup2(vn4.z), dup2(vn4.w)};
            u64 ppr[2] = {pp.x, pp.y}, ppi[2] = {pq.x, pq.y};
            u64 pur[2] = {uu.x, uu.y}, pui[2] = {uw.x, uw.y};
#pragma unroll
            for (int jp = 0; jp < 2; ++jp)
#pragma unroll
                for (int l = 0; l < 4; ++l) {
                    ArP[jp][l] = fma2(ppr[jp], vrd[l], ArP[jp][l]);
                    ArP[jp][l] = fma2(ppi[jp], vnd[l], ArP[jp][l]);
                    AiP[jp][l] = fma2(ppr[jp], vid[l], AiP[jp][l]);
                    AiP[jp][l] = fma2(ppi[jp], vrd[l], AiP[jp][l]);
                    BrP[jp][l] = fma2(pur[jp], vrd[l], BrP[jp][l]);
                    BrP[jp][l] = fma2(pui[jp], vnd[l], BrP[jp][l]);
                    BiP[jp][l] = fma2(pur[jp], vid[l], BiP[jp][l]);
                    BiP[jp][l] = fma2(pui[jp], vrd[l], BiP[jp][l]);
                }
        }
    }
    __syncthreads();

    // ---- epilogue: out = (A - mn*B)/(mx - mn) ----
    float* out_r = out;
    float* out_i = out + (long)NHEADS * S_LEN * 64;
#pragma unroll
    for (int jp = 0; jp < 2; ++jp) {
        float Ar[2][4], Ai[2][4], Br[2][4], Bi[2][4];
#pragma unroll
        for (int l = 0; l < 4; ++l) {
            float2 a = unpack2(ArP[jp][l]); Ar[0][l] = a.x; Ar[1][l] = a.y;
            float2 b = unpack2(AiP[jp][l]); Ai[0][l] = b.x; Ai[1][l] = b.y;
            float2 c = unpack2(BrP[jp][l]); Br[0][l] = c.x; Br[1][l] = c.y;
            float2 d = unpack2(BiP[jp][l]); Bi[0][l] = d.x; Bi[1][l] = d.y;
        }
#pragma unroll
        for (int e = 0; e < 2; ++e) {
            int qq = 4 * ty + 2 * jp + e;
            float mn = sm[RMN_OFF + qq];
            float mx = sm[RMX_OFF + qq];
            float sc = 1.0f / (mx - mn);
            float4 o_r, o_i;
            o_r.x = (Ar[e][0] - mn * Br[e][0]) * sc;
            o_r.y = (Ar[e][1] - mn * Br[e][1]) * sc;
            o_r.z = (Ar[e][2] - mn * Br[e][2]) * sc;
            o_r.w = (Ar[e][3] - mn * Br[e][3]) * sc;
            o_i.x = (Ai[e][0] - mn * Bi[e][0]) * sc;
            o_i.y = (Ai[e][1] - mn * Bi[e][1]) * sc;
            o_i.z = (Ai[e][2] - mn * Bi[e][2]) * sc;
            o_i.w = (Ai[e][3] - mn * Bi[e][3]) * sc;
            long g = hb + (long)(qt * 64 + qq) * 64 + 4 * tx;
            *(float4*)(out_r + g) = o_r;
            *(float4*)(out_i + g) = o_i;
        }
    }
}

extern "C" void kernel_launch(void* const* d_in, const int* in_sizes, int n_in,
                              void* d_out, int out_size)
{
    const float* qr = (const float*)d_in[0];
    const float* qi = (const float*)d_in[1];
    const float* kr = (const float*)d_in[2];
    const float* ki = (const float*)d_in[3];
    const float* vr = (const float*)d_in[4];
    const float* vi = (const float*)d_in[5];
    float* out = (float*)d_out;

    const int smem_bytes = SMEM_FLOATS * (int)sizeof(float);   // 180,736 B
    cudaFuncSetAttribute(cvattn_kernel,
                         cudaFuncAttributeMaxDynamicSharedMemorySize, smem_bytes);

    dim3 grid(S_LEN / 64, NHEADS);
    cvattn_kernel<<<grid, NTHREADS, smem_bytes>>>(qr, qi, kr, ki, vr, vi, out);
}